// round 9
// baseline (speedup 1.0000x reference)
#include <cuda_runtime.h>
#include <cuda_bf16.h>

// out[b,c,h,w] = (wcam[cam[b],c] + wident[id[b],c]) * image[b,c,h,w]
//             + (bcam[cam[b],c] + bident[id[b],c])
//
// B=32, C=3, H=W=1024, fp32. Pure HBM streaming: 384 MiB in + 384 MiB out.
// Roofline floor @ ~7 TB/s achieved: ~115 us.
//
// grid.y = plane (b*3+c), 96 planes; grid.x tiles the plane.
// VEC=4 float4s per thread at blockDim stride -> MLP=4, 128B-coalesced.
// Streaming payload uses evict-first hints (__ldcs/__stcs): single-touch
// data, no reason to occupy L2. Gather tables stay default-cached.

#define HW4   (1024 * 1024 / 4)   // float4s per plane = 262144
#define VEC   4                   // float4s per thread
#define TPB   256                 // threads per block
#define VPB   (TPB * VEC)         // float4s per block = 1024
#define BPP   (HW4 / VPB)         // blocks per plane = 256

__global__ __launch_bounds__(TPB)
void colorcal_kernel(const float4* __restrict__ img,
                     const int* __restrict__ camindex,
                     const int* __restrict__ idindex,
                     const float* __restrict__ wcam,
                     const float* __restrict__ bcam,
                     const float* __restrict__ wident,
                     const float* __restrict__ bident,
                     float4* __restrict__ out)
{
    const int plane = blockIdx.y;          // 0..95
    const int b = plane / 3;
    const int c = plane - b * 3;

    // Tiny gather: keep resident in L1/L2.
    const int cam = __ldg(&camindex[b]);
    const int idn = __ldg(&idindex[b]);
    const float w  = __ldg(&wcam[cam * 3 + c]) + __ldg(&wident[idn * 3 + c]);
    const float bb = __ldg(&bcam[cam * 3 + c]) + __ldg(&bident[idn * 3 + c]);

    // Base of this block's 1024-float4 chunk within the plane.
    const int base = plane * HW4 + blockIdx.x * VPB + threadIdx.x;

    float4 v[VEC];
#pragma unroll
    for (int j = 0; j < VEC; j++)
        v[j] = __ldcs(&img[base + j * TPB]);   // streaming load, evict-first

#pragma unroll
    for (int j = 0; j < VEC; j++) {
        float4 r;
        r.x = fmaf(w, v[j].x, bb);
        r.y = fmaf(w, v[j].y, bb);
        r.z = fmaf(w, v[j].z, bb);
        r.w = fmaf(w, v[j].w, bb);
        __stcs(&out[base + j * TPB], r);       // streaming store, evict-first
    }
}

extern "C" void kernel_launch(void* const* d_in, const int* in_sizes, int n_in,
                              void* d_out, int out_size)
{
    const float4* img      = (const float4*)d_in[0];
    const int*    camindex = (const int*)d_in[1];
    const int*    idindex  = (const int*)d_in[2];
    const float*  wcam     = (const float*)d_in[3];
    const float*  bcam     = (const float*)d_in[4];
    const float*  wident   = (const float*)d_in[5];
    const float*  bident   = (const float*)d_in[6];
    float4*       out      = (float4*)d_out;

    dim3 grid(BPP, 96, 1);   // 256 x 96 = 24576 blocks
    colorcal_kernel<<<grid, TPB>>>(img, camindex, idindex,
                                   wcam, bcam, wident, bident, out);
}

// round 16
// speedup vs baseline: 1.0024x; 1.0024x over previous
#include <cuda_runtime.h>
#include <cuda_bf16.h>

// out[b,c,h,w] = (wcam[cam[b],c] + wident[id[b],c]) * image[b,c,h,w]
//             + (bcam[cam[b],c] + bident[id[b],c])
//
// B=32, C=3, H=W=1024, fp32. Pure HBM streaming: 384 MiB in + 384 MiB out.
// R9 baseline (VEC=4): 119.6us, DRAM=84.1%, HBM 6662 GB/s.
// R10-R15: VEC=8 -> deeper per-thread MLP (8 front-batched LDG.128), half
// the CTAs, fewer coefficient gathers + wave transitions. Target 114-118us.

#define HW4   (1024 * 1024 / 4)   // float4s per plane = 262144
#define VEC   8                   // float4s per thread
#define TPB   256                 // threads per block
#define VPB   (TPB * VEC)         // float4s per block = 2048
#define BPP   (HW4 / VPB)         // blocks per plane = 128

__global__ __launch_bounds__(TPB)
void colorcal_kernel(const float4* __restrict__ img,
                     const int* __restrict__ camindex,
                     const int* __restrict__ idindex,
                     const float* __restrict__ wcam,
                     const float* __restrict__ bcam,
                     const float* __restrict__ wident,
                     const float* __restrict__ bident,
                     float4* __restrict__ out)
{
    const int plane = blockIdx.y;          // 0..95
    const int b = plane / 3;
    const int c = plane - b * 3;

    // Tiny gather: keep resident in L1/L2.
    const int cam = __ldg(&camindex[b]);
    const int idn = __ldg(&idindex[b]);
    const float w  = __ldg(&wcam[cam * 3 + c]) + __ldg(&wident[idn * 3 + c]);
    const float bb = __ldg(&bcam[cam * 3 + c]) + __ldg(&bident[idn * 3 + c]);

    // Base of this block's 2048-float4 chunk within the plane.
    const int base = plane * HW4 + blockIdx.x * VPB + threadIdx.x;

    float4 v[VEC];
#pragma unroll
    for (int j = 0; j < VEC; j++)
        v[j] = __ldcs(&img[base + j * TPB]);   // streaming load, evict-first

#pragma unroll
    for (int j = 0; j < VEC; j++) {
        float4 r;
        r.x = fmaf(w, v[j].x, bb);
        r.y = fmaf(w, v[j].y, bb);
        r.z = fmaf(w, v[j].z, bb);
        r.w = fmaf(w, v[j].w, bb);
        __stcs(&out[base + j * TPB], r);       // streaming store, evict-first
    }
}

extern "C" void kernel_launch(void* const* d_in, const int* in_sizes, int n_in,
                              void* d_out, int out_size)
{
    const float4* img      = (const float4*)d_in[0];
    const int*    camindex = (const int*)d_in[1];
    const int*    idindex  = (const int*)d_in[2];
    const float*  wcam     = (const float*)d_in[3];
    const float*  bcam     = (const float*)d_in[4];
    const float*  wident   = (const float*)d_in[5];
    const float*  bident   = (const float*)d_in[6];
    float4*       out      = (float4*)d_out;

    dim3 grid(BPP, 96, 1);   // 128 x 96 = 12288 blocks
    colorcal_kernel<<<grid, TPB>>>(img, camindex, idindex,
                                   wcam, bcam, wident, bident, out);
}